// round 5
// baseline (speedup 1.0000x reference)
#include <cuda_runtime.h>
#include <cuda_bf16.h>
#include <math.h>

// Problem constants
#define QS 256
#define LS 2048
#define NB 64
#define SS 26
#define NPOST (NB * LS * QS)     // 33,554,432
#define EM_ROWS 64
#define RENORM_MASK 15

// Per-thread A ownership (lane-split matvec):
//   warp w owns columns [32w, 32w+32); lane l owns rows {4l..4l+3, 128+4l..128+4l+3}
//   rows jj=0..4 -> fp32 packed regs (80 u64 = 160 regs)
//   row  jj=5    -> fp32 pairs in shared (16 u64 = 32 u32)
//   rows jj=6,7  -> bf16 pairs in shared (32 u32)
#define ROWPITCH_U32 68          // 64 payload u32 + 4 pad; 272B = 17*16B -> conflict-free

// ---------------------------------------------------------------------------
// Device scratch
// ---------------------------------------------------------------------------
__device__ float g_expA[QS * QS];     // exp(log_A)  [j][i]
__device__ float g_expAT[QS * QS];    // transpose
__device__ float g_expB[QS * 32];     // exp(log_B) padded
__device__ float g_pi[QS];
__device__ float g_emit[NPOST];       // [b][l][q]
__device__ float g_alpha[NPOST];
__device__ float g_beta[NPOST];
__device__ float g_Ca[NB * LS];
__device__ float g_Cb[NB * LS];
__device__ float g_loglik[NB];

// ---------------------------------------------------------------------------
// f32x2 helpers
// ---------------------------------------------------------------------------
__device__ __forceinline__ unsigned long long pk(float x, float y) {
    unsigned long long r;
    asm("mov.b64 %0, {%1,%2};" : "=l"(r) : "f"(x), "f"(y));
    return r;
}
__device__ __forceinline__ void ffma2(unsigned long long& c,
                                      unsigned long long a,
                                      unsigned long long b) {
    asm("fma.rn.f32x2 %0, %1, %2, %0;" : "+l"(c) : "l"(a), "l"(b));
}
__device__ __forceinline__ unsigned long long mul2(unsigned long long a,
                                                   unsigned long long b) {
    unsigned long long r;
    asm("mul.rn.f32x2 %0, %1, %2;" : "=l"(r) : "l"(a), "l"(b));
    return r;
}
__device__ __forceinline__ unsigned long long add2(unsigned long long a,
                                                   unsigned long long b) {
    unsigned long long r;
    asm("add.rn.f32x2 %0, %1, %2;" : "=l"(r) : "l"(a), "l"(b));
    return r;
}
__device__ __forceinline__ float2 unpk(unsigned long long u) {
    float lo, hi;
    asm("mov.b64 {%0,%1}, %2;" : "=f"(lo), "=f"(hi) : "l"(u));
    return make_float2(lo, hi);
}
__device__ __forceinline__ unsigned long long bf2f(unsigned int w) {
    unsigned int lo = w << 16;
    unsigned int hi = w & 0xffff0000u;
    unsigned long long r;
    asm("mov.b64 %0, {%1,%2};" : "=l"(r) : "r"(lo), "r"(hi));
    return r;
}
__device__ __forceinline__ unsigned int pack_bf16(float a, float b) {
    __nv_bfloat16 b0 = __float2bfloat16(a);
    __nv_bfloat16 b1 = __float2bfloat16(b);
    return (unsigned int)__bfloat16_as_ushort(b0) |
           ((unsigned int)__bfloat16_as_ushort(b1) << 16);
}

// ---------------------------------------------------------------------------
// Kernel 0: exp() of parameters
// ---------------------------------------------------------------------------
__global__ void precompute_kernel(const float* __restrict__ log_A,
                                  const float* __restrict__ log_pi,
                                  const float* __restrict__ log_B) {
    int idx = blockIdx.x * 256 + threadIdx.x;
    if (blockIdx.x < 256) {
        float v = expf(log_A[idx]);
        g_expA[idx] = v;
        int j = idx >> 8, i = idx & 255;
        g_expAT[i * QS + j] = v;
    } else if (blockIdx.x < 282) {
        int k = idx - 65536;
        if (k < QS * SS) {
            int q = k / SS, s = k - q * SS;
            g_expB[q * 32 + s] = expf(log_B[k]);
        }
    } else {
        if (threadIdx.x < QS) g_pi[threadIdx.x] = expf(log_pi[threadIdx.x]);
    }
}

// ---------------------------------------------------------------------------
// Kernel 1: emission GEMM
// ---------------------------------------------------------------------------
__global__ void __launch_bounds__(256) emission_kernel(const float* __restrict__ inputs) {
    __shared__ float in_sh[EM_ROWS][SS];
    int tid = threadIdx.x;
    int row0 = blockIdx.x * EM_ROWS;

    for (int i = tid; i < EM_ROWS * SS; i += 256)
        in_sh[i / SS][i % SS] = inputs[row0 * SS + i];
    float eb[SS];
#pragma unroll
    for (int s = 0; s < SS; s++) eb[s] = g_expB[tid * 32 + s];
    __syncthreads();

#pragma unroll 4
    for (int r = 0; r < EM_ROWS; r++) {
        float acc = 0.0f;
#pragma unroll
        for (int s = 0; s < SS; s++) acc = fmaf(in_sh[r][s], eb[s], acc);
        g_emit[(size_t)(row0 + r) * QS + tid] = acc;
    }
}

// ---------------------------------------------------------------------------
// Block reduction (renorm steps only)
// ---------------------------------------------------------------------------
__device__ __forceinline__ float block_sum(float v, float* red, int tid) {
#pragma unroll
    for (int o = 16; o > 0; o >>= 1) v += __shfl_xor_sync(0xffffffffu, v, o);
    if ((tid & 31) == 0) red[tid >> 5] = v;
    __syncthreads();
    float s = 0.0f;
#pragma unroll
    for (int w = 0; w < 8; w++) s += red[w];
    return s;
}

// ---------------------------------------------------------------------------
// Lane-split matvec: returns v[tid] = sum_j A[j][tid] * p[j]
//   Areg  : 80 u64 = rows jj0..4 (fp32), layout Areg[jj*16+m]
//   myrow : u32 [0,32)=row jj5 fp32 pairs, [32,48)=jj6 bf16, [48,64)=jj7 bf16
//   p_sh  : current p vector in shared
// ---------------------------------------------------------------------------
__device__ __forceinline__ float matvec_lane(const unsigned long long* __restrict__ Areg,
                                             const unsigned int* __restrict__ myrow,
                                             const float* __restrict__ p_sh,
                                             int lane) {
    const float4* p4buf = (const float4*)p_sh;
    float4 pa = p4buf[lane];        // p[4l .. 4l+3]
    float4 pb = p4buf[32 + lane];   // p[128+4l .. 128+4l+3]

    unsigned long long acc[16];
    unsigned long long pp;

    // jj = 0 (mul, initializes acc)
    pp = pk(pa.x, pa.x);
#pragma unroll
    for (int m = 0; m < 16; m++) acc[m] = mul2(Areg[m], pp);
    // jj = 1..3
    pp = pk(pa.y, pa.y);
#pragma unroll
    for (int m = 0; m < 16; m++) ffma2(acc[m], Areg[16 + m], pp);
    pp = pk(pa.z, pa.z);
#pragma unroll
    for (int m = 0; m < 16; m++) ffma2(acc[m], Areg[32 + m], pp);
    pp = pk(pa.w, pa.w);
#pragma unroll
    for (int m = 0; m < 16; m++) ffma2(acc[m], Areg[48 + m], pp);
    // jj = 4
    pp = pk(pb.x, pb.x);
#pragma unroll
    for (int m = 0; m < 16; m++) ffma2(acc[m], Areg[64 + m], pp);

    // jj = 5: fp32 pairs from shared (8 x LDS.128)
    pp = pk(pb.y, pb.y);
    const ulonglong2* a5 = (const ulonglong2*)myrow;
#pragma unroll
    for (int k = 0; k < 8; k++) {
        ulonglong2 w = a5[k];
        ffma2(acc[2 * k],     w.x, pp);
        ffma2(acc[2 * k + 1], w.y, pp);
    }
    // jj = 6,7: bf16 pairs from shared (8 x LDS.128)
    {
        unsigned long long pp6 = pk(pb.z, pb.z);
        const uint4* a6 = (const uint4*)(myrow + 32);
#pragma unroll
        for (int k = 0; k < 4; k++) {
            uint4 w = a6[k];
            ffma2(acc[4 * k + 0], bf2f(w.x), pp6);
            ffma2(acc[4 * k + 1], bf2f(w.y), pp6);
            ffma2(acc[4 * k + 2], bf2f(w.z), pp6);
            ffma2(acc[4 * k + 3], bf2f(w.w), pp6);
        }
        unsigned long long pp7 = pk(pb.w, pb.w);
        const uint4* a7 = (const uint4*)(myrow + 48);
#pragma unroll
        for (int k = 0; k < 4; k++) {
            uint4 w = a7[k];
            ffma2(acc[4 * k + 0], bf2f(w.x), pp7);
            ffma2(acc[4 * k + 1], bf2f(w.y), pp7);
            ffma2(acc[4 * k + 2], bf2f(w.z), pp7);
            ffma2(acc[4 * k + 3], bf2f(w.w), pp7);
        }
    }

    // Cross-lane reduce: 5 butterfly stages; lane l ends with column (32w + l).
    const unsigned FULL = 0xffffffffu;
    unsigned long long r8[8];
    {
        bool hi = (lane & 16) != 0;
#pragma unroll
        for (int i = 0; i < 8; i++) {
            unsigned long long k = hi ? acc[8 + i] : acc[i];
            unsigned long long g = hi ? acc[i] : acc[8 + i];
            r8[i] = add2(k, __shfl_xor_sync(FULL, g, 16));
        }
    }
    unsigned long long r4[4];
    {
        bool hi = (lane & 8) != 0;
#pragma unroll
        for (int i = 0; i < 4; i++) {
            unsigned long long k = hi ? r8[4 + i] : r8[i];
            unsigned long long g = hi ? r8[i] : r8[4 + i];
            r4[i] = add2(k, __shfl_xor_sync(FULL, g, 8));
        }
    }
    unsigned long long r2[2];
    {
        bool hi = (lane & 4) != 0;
#pragma unroll
        for (int i = 0; i < 2; i++) {
            unsigned long long k = hi ? r4[2 + i] : r4[i];
            unsigned long long g = hi ? r4[i] : r4[2 + i];
            r2[i] = add2(k, __shfl_xor_sync(FULL, g, 4));
        }
    }
    unsigned long long r1;
    {
        bool hi = (lane & 2) != 0;
        unsigned long long k = hi ? r2[1] : r2[0];
        unsigned long long g = hi ? r2[0] : r2[1];
        r1 = add2(k, __shfl_xor_sync(FULL, g, 2));
    }
    unsigned long long tot = add2(r1, __shfl_xor_sync(FULL, r1, 1));
    float2 f = unpk(tot);
    return (lane & 1) ? f.y : f.x;
}

// ---------------------------------------------------------------------------
// Kernel 2: scaled forward/backward, deferred renormalization.
// ---------------------------------------------------------------------------
extern __shared__ float sh[];

#define SH_A_U32   ((unsigned int*)sh)
#define SH_P(buf)  (sh + QS * ROWPITCH_U32 + (buf) * QS)
#define SH_RED     (sh + QS * ROWPITCH_U32 + 2 * QS)

__global__ void __launch_bounds__(256, 1) fb_kernel() {
    int tid = threadIdx.x;
    int lane = tid & 31;
    int c0 = tid & ~31;               // warp's column base = 32*w
    int bx = blockIdx.x;
    bool fwd = (bx < NB);
    int b = fwd ? bx : bx - NB;
    const float* Ag = fwd ? g_expA : g_expAT;

    // rows jj=0..4 -> fp32 register pairs over columns (c0+2m, c0+2m+1)
    unsigned long long Areg[80];
#pragma unroll
    for (int jj = 0; jj < 5; jj++) {
        int j = (jj < 4) ? (4 * lane + jj) : (128 + 4 * lane);
        const float* row = Ag + j * QS + c0;
#pragma unroll
        for (int m = 0; m < 16; m++)
            Areg[jj * 16 + m] = pk(row[2 * m], row[2 * m + 1]);
    }

    // rows jj=5 (fp32) and jj=6,7 (bf16) -> this thread's private shared row
    unsigned int* myrow = SH_A_U32 + tid * ROWPITCH_U32;
    {
        const float* r5 = Ag + (128 + 4 * lane + 1) * QS + c0;
        const float* r6 = Ag + (128 + 4 * lane + 2) * QS + c0;
        const float* r7 = Ag + (128 + 4 * lane + 3) * QS + c0;
        for (int m = 0; m < 16; m++) {
            ((float2*)myrow)[m] = make_float2(r5[2 * m], r5[2 * m + 1]);
            myrow[32 + m] = pack_bf16(r6[2 * m], r6[2 * m + 1]);
            myrow[48 + m] = pack_bf16(r7[2 * m], r7[2 * m + 1]);
        }
    }

    const float* em_b = g_emit + (size_t)b * LS * QS;
    float* st_b = (fwd ? g_alpha : g_beta) + (size_t)b * LS * QS;
    float* C_b  = (fwd ? g_Ca : g_Cb) + b * LS;
    float* red  = SH_RED;

    double C = 0.0;
    int cur = 0;

    if (fwd) {
        float v = g_pi[tid] * em_b[tid];
        st_b[tid] = v;
        if (tid == 0) C_b[0] = 0.0f;
        SH_P(0)[tid] = v;
        __syncthreads();

        for (int t = 1; t < LS; t++) {
            float e  = em_b[(size_t)t * QS + tid];
            float mv = matvec_lane(Areg, myrow, SH_P(cur), lane);
            float v2 = mv * e;
            float Ct = (float)C;
            float pn = v2;
            if ((t & RENORM_MASK) == RENORM_MASK) {
                float s = block_sum(v2, red, tid);
                pn = v2 * (1.0f / s);
                if (t == LS - 1 && tid == 0)
                    g_loglik[b] = (float)(C + (double)logf(s));
                C += (double)logf(s);
            }
            SH_P(cur ^ 1)[tid] = pn;
            __syncthreads();
            st_b[(size_t)t * QS + tid] = v2;
            if (tid == 0) C_b[t] = Ct;
            cur ^= 1;
        }
    } else {
        st_b[(size_t)(LS - 1) * QS + tid] = 1.0f;
        if (tid == 0) C_b[LS - 1] = 0.0f;
        SH_P(0)[tid] = em_b[(size_t)(LS - 1) * QS + tid];
        __syncthreads();

        for (int t = LS - 2; t >= 0; t--) {
            float e = em_b[(size_t)t * QS + tid];
            float v = matvec_lane(Areg, myrow, SH_P(cur), lane);
            float Ct = (float)C;
            float q = v;
            if ((t & RENORM_MASK) == 0) {
                float s = block_sum(v, red, tid);
                q = v * (1.0f / s);
                C += (double)logf(s);
            }
            SH_P(cur ^ 1)[tid] = e * q;
            __syncthreads();
            st_b[(size_t)t * QS + tid] = v;
            if (tid == 0) C_b[t] = Ct;
            cur ^= 1;
        }
    }
}

// ---------------------------------------------------------------------------
// Kernel 3: posterior + loglik
// ---------------------------------------------------------------------------
__global__ void __launch_bounds__(256) posterior_kernel(float* __restrict__ out, int out_size) {
    int i4 = blockIdx.x * 256 + threadIdx.x;
    int idx = i4 << 2;
    int bt = idx >> 8;
    int b  = bt >> 11;
    float4 a  = *(const float4*)(g_alpha + idx);
    float4 be = *(const float4*)(g_beta + idx);
    float c = g_Ca[bt] + g_Cb[bt] - g_loglik[b];
    float4 o;
    o.x = logf(a.x * be.x) + c;
    o.y = logf(a.y * be.y) + c;
    o.z = logf(a.z * be.z) + c;
    o.w = logf(a.w * be.w) + c;
    *(float4*)(out + idx) = o;
    if (i4 < NB && out_size >= NPOST + NB)
        out[NPOST + i4] = g_loglik[i4];
}

// ---------------------------------------------------------------------------
// Launch
// ---------------------------------------------------------------------------
extern "C" void kernel_launch(void* const* d_in, const int* in_sizes, int n_in,
                              void* d_out, int out_size) {
    const float* inputs = (const float*)d_in[0];   // (1,64,2048,26)
    const float* log_A  = (const float*)d_in[1];   // (1,256,256)
    const float* log_pi = (const float*)d_in[2];   // (1,256)
    const float* log_B  = (const float*)d_in[3];   // (1,256,26)
    float* out = (float*)d_out;

    precompute_kernel<<<283, 256>>>(log_A, log_pi, log_B);
    emission_kernel<<<(NB * LS) / EM_ROWS, 256>>>(inputs);

    int smem = (QS * ROWPITCH_U32 + 2 * QS + 16) * (int)sizeof(float);
    cudaFuncSetAttribute(fb_kernel, cudaFuncAttributeMaxDynamicSharedMemorySize, smem);
    fb_kernel<<<2 * NB, 256, smem>>>();

    posterior_kernel<<<NPOST / 1024, 256>>>(out, out_size);
}